// round 13
// baseline (speedup 1.0000x reference)
#include <cuda_runtime.h>
#include <cstdint>

#define HEADS 8
#define BATCH 8
#define SEQ   1024
#define HID   512
#define DK    64
#define NH    (HEADS*BATCH)   /* 64 */
#define TOPK  51
#define SCALE 1.2f

#define SSTRIDE 1028          /* x4B multiple of 16 -> float4-aligned rows, banks spread */

// ---------------- device scratch (allocation-free) ----------------
__device__ float g_Qt[(size_t)NH * DK * SEQ];      // [n][c][s]
__device__ float g_Kt[(size_t)NH * DK * SEQ];      // [n][c][s]
__device__ float g_V [(size_t)NH * SEQ * DK];      // [n][s][c]
__device__ float g_attn[(size_t)BATCH * SEQ * HID];// [b][s][h*64+c]

// ---------------- cp.async helpers ----------------
__device__ __forceinline__ void cp16(float* dst, const float* src) {
    unsigned u = (unsigned)__cvta_generic_to_shared(dst);
    asm volatile("cp.async.cg.shared.global [%0], [%1], 16;\n" :: "r"(u), "l"(src));
}
__device__ __forceinline__ void cp_commit() { asm volatile("cp.async.commit_group;\n" ::: "memory"); }
__device__ __forceinline__ void cp_wait1()  { asm volatile("cp.async.wait_group 1;\n" ::: "memory"); }
__device__ __forceinline__ void cp_wait0()  { asm volatile("cp.async.wait_group 0;\n" ::: "memory"); }

__device__ __forceinline__ float ex2f(float x) {
    float r; asm("ex2.approx.ftz.f32 %0, %1;" : "=f"(r) : "f"(x)); return r;
}

// =================================================================
// SGEMM: C[8192,512] = X[8192,512] @ W[512,512] + bias (at FFMA roofline)
// mode 0: out[(h*8+b)][c][s]   mode 1: out[(h*8+b)][s][c]   mode 2: out[m][n]
// =================================================================
__global__ void __launch_bounds__(256) sgemm512(
    const float* __restrict__ X, const float* __restrict__ W,
    const float* __restrict__ bias, float* __restrict__ out, int mode)
{
    __shared__ float As[16][68];
    __shared__ float Bs[16][64];

    const int tid = threadIdx.x;
    const int tx = tid & 15, ty = tid >> 4;
    const int bm = blockIdx.y * 64, bn = blockIdx.x * 64;

    const int am = tid >> 2, ak = (tid & 3) << 2;
    const int wk = tid >> 4, wn = (tid & 15) << 2;

    float acc[4][4] = {};

    for (int k0 = 0; k0 < 512; k0 += 16) {
        float4 xa = *(const float4*)&X[(bm + am) * 512 + k0 + ak];
        float4 wb = *(const float4*)&W[(k0 + wk) * 512 + bn + wn];
        __syncthreads();
        As[ak + 0][am] = xa.x; As[ak + 1][am] = xa.y;
        As[ak + 2][am] = xa.z; As[ak + 3][am] = xa.w;
        *(float4*)&Bs[wk][wn] = wb;
        __syncthreads();
#pragma unroll
        for (int kk = 0; kk < 16; kk++) {
            const float4 a4 = *(const float4*)&As[kk][ty * 4];
            const float4 b4 = *(const float4*)&Bs[kk][tx * 4];
            const float a[4] = {a4.x, a4.y, a4.z, a4.w};
            const float b[4] = {b4.x, b4.y, b4.z, b4.w};
#pragma unroll
            for (int i = 0; i < 4; i++)
#pragma unroll
                for (int j = 0; j < 4; j++)
                    acc[i][j] = fmaf(a[i], b[j], acc[i][j]);
        }
    }

    const float4 bb4 = *(const float4*)(bias + bn + tx * 4);
    const float bb[4] = {bb4.x, bb4.y, bb4.z, bb4.w};
    const int m0 = bm + ty * 4;
    const int n0 = bn + tx * 4;

    if (mode == 2) {
#pragma unroll
        for (int i = 0; i < 4; i++) {
            float4 o = make_float4(acc[i][0] + bb[0], acc[i][1] + bb[1],
                                   acc[i][2] + bb[2], acc[i][3] + bb[3]);
            *(float4*)(out + (m0 + i) * 512 + n0) = o;
        }
    } else if (mode == 1) {  // V: [(h*8+b)][s][c]
        const int h = n0 >> 6, c = n0 & 63;
        const int b_ = m0 >> 10, s = m0 & 1023;
        float* base = out + ((h * 8 + b_) * SEQ + s) * DK + c;
#pragma unroll
        for (int i = 0; i < 4; i++) {
            float4 o = make_float4(acc[i][0] + bb[0], acc[i][1] + bb[1],
                                   acc[i][2] + bb[2], acc[i][3] + bb[3]);
            *(float4*)(base + i * DK) = o;
        }
    } else {                 // Q/K transposed: [(h*8+b)][c][s]
        const int h = n0 >> 6;
        const int b_ = m0 >> 10, s = m0 & 1023;
        float* base = out + (h * 8 + b_) * DK * SEQ + s;
#pragma unroll
        for (int j = 0; j < 4; j++) {
            const int c = (n0 & 63) + j;
            float4 o = make_float4(acc[0][j] + bb[j], acc[1][j] + bb[j],
                                   acc[2][j] + bb[j], acc[3][j] + bb[j]);
            *(float4*)(base + c * SEQ) = o;
        }
    }
}

// =================================================================
// Fused attention, 1024 threads (8 warps/SMSP). One CTA = 32 queries
// of one n = h*8+b. Same phases as R9, halved per-thread tiles.
// =================================================================
#define KVBUF 8704                                           /* floats */
#define SQ_FLOATS 2048
#define SS_FLOATS (32 * SSTRIDE)                             /* 32896 */
#define ATTN_SMEM_BYTES ((SQ_FLOATS + SS_FLOATS + 2*KVBUF) * 4) /* 209408 */

__device__ __forceinline__ void load_k_chunk(float* buf, const float* gK, int kc, int tid) {
#pragma unroll
    for (int j = 0; j < 2; j++) {                     // 2048 float4 / 1024 thr
        int f = tid + 1024 * j;
        int c = f >> 5;
        int kk = (f & 31) << 2;
        cp16(buf + c * 128 + kk, gK + c * SEQ + kc * 128 + kk);
    }
}
__device__ __forceinline__ void load_v_chunk(float* buf, const float* gV, int kc, int tid) {
#pragma unroll
    for (int j = 0; j < 2; j++) {
        int f = tid + 1024 * j;
        int key = f >> 4;
        int c4 = (f & 15) << 2;
        cp16(buf + key * 68 + c4, gV + (kc * 128 + key) * DK + c4);
    }
}

__global__ void __launch_bounds__(1024, 1) attn_kernel(const int* __restrict__ randidx, int n_rand)
{
    extern __shared__ float sm[];
    float* sQt  = sm;                        // [64][32]
    float* sS   = sm + SQ_FLOATS;            // [32][SSTRIDE]
    float* sKV0 = sm + SQ_FLOATS + SS_FLOATS;
    float* sKV1 = sKV0 + KVBUF;
    __shared__ unsigned sRand[32];

    const int tid  = threadIdx.x;
    const int lane = tid & 31;
    const int warp = tid >> 5;               // 0..31
    const int qb = blockIdx.x;               // 0..31
    const int n  = blockIdx.y;               // h*8 + b

    const float* gQ = g_Qt + n * (DK * SEQ);
    const float* gK = g_Kt + n * (DK * SEQ);
    const float* gV = g_V  + n * (SEQ * DK);

    load_k_chunk(sKV0, gK, 0, tid);          // kick off K chunk 0
    cp_commit();

    if (tid < 32) sRand[tid] = 0u;
    if (tid < 512) {  // Q tile (pre-scaled by 1/sqrt(64)): 512 float4
        int c = tid >> 3, s4 = (tid & 7) << 2;
        float4 v = *(const float4*)(gQ + c * SEQ + qb * 32 + s4);
        v.x *= 0.125f; v.y *= 0.125f; v.z *= 0.125f; v.w *= 0.125f;
        *(float4*)(sQt + c * 32 + s4) = v;
    }
    __syncthreads();
    if (tid < n_rand) {
        int v = randidx[tid] & (SEQ - 1);
        atomicOr(&sRand[v >> 5], 1u << (v & 31));
    }

    // ---- scores: thread = 2 rows x 2 keys ----
    {
        const int rowg = tid & 15;           // Q float2: 16 distinct/warp (1 phase)
        const int keyg = tid >> 4;           // 0..63; K float2: 2 distinct/warp
        const int r0 = rowg * 2;
        const int key0 = keyg * 2;
        const float* qp = sQt + r0;
        for (int kc = 0; kc < 8; kc++) {
            if (kc < 7) {
                load_k_chunk((kc & 1) ? sKV0 : sKV1, gK, kc + 1, tid);
                cp_commit();
                cp_wait1();
            } else {
                cp_wait0();
            }
            __syncthreads();
            const float* kp = ((kc & 1) ? sKV1 : sKV0) + key0;
            float a00 = 0.f, a01 = 0.f, a10 = 0.f, a11 = 0.f;
#pragma unroll 16
            for (int c = 0; c < 64; c++) {
                const float2 q  = *(const float2*)(qp + c * 32);   // 16-way dedup
                const float2 k2 = *(const float2*)(kp + c * 128);  // 2-way dedup
                a00 = fmaf(q.x, k2.x, a00); a01 = fmaf(q.x, k2.y, a01);
                a10 = fmaf(q.y, k2.x, a10); a11 = fmaf(q.y, k2.y, a11);
            }
            float* sp = sS + r0 * SSTRIDE + kc * 128 + key0;
            *(float2*)(sp)           = make_float2(a00, a01);
            *(float2*)(sp + SSTRIDE) = make_float2(a10, a11);
            __syncthreads();
        }
    }

    load_v_chunk(sKV0, gV, 0, tid);          // prefetch V chunk 0 (overlaps topk)
    cp_commit();

    // ---- exp + exact top-51 (early-exit radix) + rand-mask + renorm ----
    {
        const int r = warp;                  // 1 row per warp
        float* row = sS + r * SSTRIDE;
        float e[32];
        float m = -3.0e38f;
#pragma unroll
        for (int i = 0; i < 32; i++) { e[i] = row[lane + 32 * i]; m = fmaxf(m, e[i]); }
#pragma unroll
        for (int off = 16; off; off >>= 1) m = fmaxf(m, __shfl_xor_sync(0xFFFFFFFFu, m, off));
#pragma unroll
        for (int i = 0; i < 32; i++) e[i] = ex2f((e[i] - m) * 1.4426950408889634f);

        // exact 51st-largest threshold; stop as soon as count == TOPK
        unsigned prefix = 0u;
#pragma unroll 1
        for (int bit = 29; bit >= 0; bit--) {
            const unsigned cand = prefix | (1u << bit);
            int c = 0;
#pragma unroll
            for (int i = 0; i < 32; i++) c += (__float_as_uint(e[i]) >= cand) ? 1 : 0;
            c = __reduce_add_sync(0xFFFFFFFFu, c);
            if (c >= TOPK) {
                prefix = cand;
                if (c == TOPK) break;       // exact set resolved
            }
        }

        float s = 0.0f;
#pragma unroll
        for (int i = 0; i < 32; i++) {
            bool sel = (__float_as_uint(e[i]) >= prefix) || ((sRand[i] >> lane) & 1u);
            e[i] = sel ? e[i] * SCALE : e[i];
            s += e[i];
        }
#pragma unroll
        for (int off = 16; off; off >>= 1) s += __shfl_xor_sync(0xFFFFFFFFu, s, off);
        const float inv = 1.0f / s;
#pragma unroll
        for (int i = 0; i < 32; i++) row[lane + 32 * i] = e[i] * inv;
    }

    // ---- AV: thread = 2 rows x 4 cols, 4-way k-split, smem reduce ----
    {
        const int t256 = tid & 255;
        const int rowg = t256 & 15;          // 2 rows each -> 32 rows
        const int colg = (t256 >> 4) & 15;   // 4 cols each -> 64 cols
        const int kq   = tid >> 8;           // 0..3: k-quarter of each chunk
        const int r0 = rowg * 2;
        const int c0 = colg * 4;
        const int kb = kq * 32;
        float acc[2][4] = {};
        for (int kc = 0; kc < 8; kc++) {
            if (kc < 7) {
                load_v_chunk((kc & 1) ? sKV0 : sKV1, gV, kc + 1, tid);
                cp_commit();
                cp_wait1();
            } else {
                cp_wait0();
            }
            __syncthreads();
            const float* Vb = ((kc & 1) ? sKV1 : sKV0) + c0;
            const float* Sb = sS + r0 * SSTRIDE + kc * 128;
#pragma unroll 4
            for (int k = kb; k < kb + 32; k += 4) {
                const float4 s0 = *(const float4*)(Sb + k);            // aligned
                const float4 s1 = *(const float4*)(Sb + SSTRIDE + k);
                const float4 v0 = *(const float4*)(Vb + (k + 0) * 68);
                const float4 v1 = *(const float4*)(Vb + (k + 1) * 68);
                const float4 v2 = *(const float4*)(Vb + (k + 2) * 68);
                const float4 v3 = *(const float4*)(Vb + (k + 3) * 68);
                const float a0[4] = {s0.x, s0.y, s0.z, s0.w};
                const float a1[4] = {s1.x, s1.y, s1.z, s1.w};
                const float4 vv[4] = {v0, v1, v2, v3};
#pragma unroll
                for (int t = 0; t < 4; t++) {
                    acc[0][0] = fmaf(a0[t], vv[t].x, acc[0][0]);
                    acc[0][1] = fmaf(a0[t], vv[t].y, acc[0][1]);
                    acc[0][2] = fmaf(a0[t], vv[t].z, acc[0][2]);
                    acc[0][3] = fmaf(a0[t], vv[t].w, acc[0][3]);
                    acc[1][0] = fmaf(a1[t], vv[t].x, acc[1][0]);
                    acc[1][1] = fmaf(a1[t], vv[t].y, acc[1][1]);
                    acc[1][2] = fmaf(a1[t], vv[t].z, acc[1][2]);
                    acc[1][3] = fmaf(a1[t], vv[t].w, acc[1][3]);
                }
            }
            __syncthreads();
        }

        // reduce the 4 kq-partials through sKV0 (free after last V chunk)
        float* scratch = sKV0;
        if (kq != 0) {
            float* dst = scratch + ((kq - 1) * 256 + t256) * 8;
            *(float4*)(dst)     = make_float4(acc[0][0], acc[0][1], acc[0][2], acc[0][3]);
            *(float4*)(dst + 4) = make_float4(acc[1][0], acc[1][1], acc[1][2], acc[1][3]);
        }
        __syncthreads();
        if (kq == 0) {
#pragma unroll
            for (int p = 0; p < 3; p++) {
                const float* src = scratch + (p * 256 + t256) * 8;
                const float4 t0 = *(const float4*)(src);
                const float4 t1 = *(const float4*)(src + 4);
                acc[0][0] += t0.x; acc[0][1] += t0.y; acc[0][2] += t0.z; acc[0][3] += t0.w;
                acc[1][0] += t1.x; acc[1][1] += t1.y; acc[1][2] += t1.z; acc[1][3] += t1.w;
            }
            // write to g_attn[b][s][h*64+c]
            const int h = n >> 3, b_ = n & 7;
            const int s = qb * 32 + r0;
            float* ob = g_attn + (b_ * SEQ + s) * HID + h * 64 + c0;
            *(float4*)(ob)       = make_float4(acc[0][0], acc[0][1], acc[0][2], acc[0][3]);
            *(float4*)(ob + HID) = make_float4(acc[1][0], acc[1][1], acc[1][2], acc[1][3]);
        }
    }
}

// =================================================================
extern "C" void kernel_launch(void* const* d_in, const int* in_sizes, int n_in,
                              void* d_out, int out_size) {
    const float* Qx  = (const float*)d_in[0];
    const float* KVx = (const float*)d_in[1];
    const float* Wq  = (const float*)d_in[2];
    const float* bq  = (const float*)d_in[3];
    const float* Wk  = (const float*)d_in[4];
    const float* bk  = (const float*)d_in[5];
    const float* Wv  = (const float*)d_in[6];
    const float* bv  = (const float*)d_in[7];
    const float* Wo  = (const float*)d_in[8];
    const float* bo  = (const float*)d_in[9];
    const int* ridx  = (const int*)d_in[10];
    const int n_rand = in_sizes[10];
    float* out = (float*)d_out;

    float *pQt, *pKt, *pV, *pA;
    cudaGetSymbolAddress((void**)&pQt, g_Qt);
    cudaGetSymbolAddress((void**)&pKt, g_Kt);
    cudaGetSymbolAddress((void**)&pV,  g_V);
    cudaGetSymbolAddress((void**)&pA,  g_attn);

    cudaFuncSetAttribute(attn_kernel, cudaFuncAttributeMaxDynamicSharedMemorySize, ATTN_SMEM_BYTES);

    dim3 gg(8, 128);   // N tiles (512/64), M tiles (8192/64)
    sgemm512<<<gg, 256>>>(Qx,  Wq, bq, pQt, 0);
    sgemm512<<<gg, 256>>>(KVx, Wk, bk, pKt, 0);
    sgemm512<<<gg, 256>>>(KVx, Wv, bv, pV,  1);
    attn_kernel<<<dim3(32, 64), 1024, ATTN_SMEM_BYTES>>>(ridx, n_rand);
    sgemm512<<<gg, 256>>>(pA, Wo, bo, out, 2);
}

// round 14
// speedup vs baseline: 1.2289x; 1.2289x over previous
#include <cuda_runtime.h>
#include <cstdint>

#define HEADS 8
#define BATCH 8
#define SEQ   1024
#define HID   512
#define DK    64
#define NH    (HEADS*BATCH)   /* 64 */
#define TOPK  51
#define SCALE 1.2f

#define SSTRIDE 1025          /* odd: conflict-free row access (R9 proven) */

// ---------------- device scratch (allocation-free) ----------------
__device__ float g_Qt[(size_t)NH * DK * SEQ];      // [n][c][s]
__device__ float g_Kt[(size_t)NH * DK * SEQ];      // [n][c][s]
__device__ float g_V [(size_t)NH * SEQ * DK];      // [n][s][c]
__device__ float g_attn[(size_t)BATCH * SEQ * HID];// [b][s][h*64+c]

// ---------------- cp.async helpers ----------------
__device__ __forceinline__ void cp16(float* dst, const float* src) {
    unsigned u = (unsigned)__cvta_generic_to_shared(dst);
    asm volatile("cp.async.cg.shared.global [%0], [%1], 16;\n" :: "r"(u), "l"(src));
}
__device__ __forceinline__ void cp_commit() { asm volatile("cp.async.commit_group;\n" ::: "memory"); }
__device__ __forceinline__ void cp_wait1()  { asm volatile("cp.async.wait_group 1;\n" ::: "memory"); }
__device__ __forceinline__ void cp_wait0()  { asm volatile("cp.async.wait_group 0;\n" ::: "memory"); }

__device__ __forceinline__ float ex2f(float x) {
    float r; asm("ex2.approx.ftz.f32 %0, %1;" : "=f"(r) : "f"(x)); return r;
}

// ---------------- packed f32x2 FMA (Blackwell FFMA2) ----------------
__device__ __forceinline__ uint64_t dup2(float x) {
    uint64_t r; asm("mov.b64 %0, {%1, %1};" : "=l"(r) : "f"(x)); return r;
}
__device__ __forceinline__ void fma2(uint64_t& d, uint64_t a, uint64_t b) {
    asm("fma.rn.f32x2 %0, %1, %2, %0;" : "+l"(d) : "l"(a), "l"(b));
}
__device__ __forceinline__ float2 unpack2(uint64_t v) {
    float2 r; asm("mov.b64 {%0, %1}, %2;" : "=f"(r.x), "=f"(r.y) : "l"(v)); return r;
}

// =================================================================
// SGEMM: C[8192,512] = X[8192,512] @ W[512,512] + bias, FFMA2 core
// mode 0: out[(h*8+b)][c][s]   mode 1: out[(h*8+b)][s][c]   mode 2: out[m][n]
// =================================================================
__global__ void __launch_bounds__(256) sgemm512(
    const float* __restrict__ X, const float* __restrict__ W,
    const float* __restrict__ bias, float* __restrict__ out, int mode)
{
    __shared__ float As[16][68];
    __shared__ float Bs[16][64];

    const int tid = threadIdx.x;
    const int tx = tid & 15, ty = tid >> 4;
    const int bm = blockIdx.y * 64, bn = blockIdx.x * 64;

    const int am = tid >> 2, ak = (tid & 3) << 2;
    const int wk = tid >> 4, wn = (tid & 15) << 2;

    uint64_t acc[4][2] = {};           // [row][col-pair], packed f32x2

    for (int k0 = 0; k0 < 512; k0 += 16) {
        float4 xa = *(const float4*)&X[(bm + am) * 512 + k0 + ak];
        float4 wb = *(const float4*)&W[(k0 + wk) * 512 + bn + wn];
        __syncthreads();
        As[ak + 0][am] = xa.x; As[ak + 1][am] = xa.y;
        As[ak + 2][am] = xa.z; As[ak + 3][am] = xa.w;
        *(float4*)&Bs[wk][wn] = wb;
        __syncthreads();
#pragma unroll
        for (int kk = 0; kk < 16; kk++) {
            const float4 a4 = *(const float4*)&As[kk][ty * 4];
            const ulonglong2 b2 = *(const ulonglong2*)&Bs[kk][tx * 4];  // (b0,b1),(b2,b3)
            const uint64_t d0 = dup2(a4.x), d1 = dup2(a4.y), d2 = dup2(a4.z), d3 = dup2(a4.w);
            fma2(acc[0][0], d0, b2.x); fma2(acc[0][1], d0, b2.y);
            fma2(acc[1][0], d1, b2.x); fma2(acc[1][1], d1, b2.y);
            fma2(acc[2][0], d2, b2.x); fma2(acc[2][1], d2, b2.y);
            fma2(acc[3][0], d3, b2.x); fma2(acc[3][1], d3, b2.y);
        }
    }

    float accf[4][4];
#pragma unroll
    for (int i = 0; i < 4; i++) {
        const float2 p0 = unpack2(acc[i][0]);
        const float2 p1 = unpack2(acc[i][1]);
        accf[i][0] = p0.x; accf[i][1] = p0.y; accf[i][2] = p1.x; accf[i][3] = p1.y;
    }

    const float4 bb4 = *(const float4*)(bias + bn + tx * 4);
    const float bb[4] = {bb4.x, bb4.y, bb4.z, bb4.w};
    const int m0 = bm + ty * 4;
    const int n0 = bn + tx * 4;

    if (mode == 2) {
#pragma unroll
        for (int i = 0; i < 4; i++) {
            float4 o = make_float4(accf[i][0] + bb[0], accf[i][1] + bb[1],
                                   accf[i][2] + bb[2], accf[i][3] + bb[3]);
            *(float4*)(out + (m0 + i) * 512 + n0) = o;
        }
    } else if (mode == 1) {  // V: [(h*8+b)][s][c]
        const int h = n0 >> 6, c = n0 & 63;
        const int b_ = m0 >> 10, s = m0 & 1023;
        float* base = out + ((h * 8 + b_) * SEQ + s) * DK + c;
#pragma unroll
        for (int i = 0; i < 4; i++) {
            float4 o = make_float4(accf[i][0] + bb[0], accf[i][1] + bb[1],
                                   accf[i][2] + bb[2], accf[i][3] + bb[3]);
            *(float4*)(base + i * DK) = o;
        }
    } else {                 // Q/K transposed: [(h*8+b)][c][s]
        const int h = n0 >> 6;
        const int b_ = m0 >> 10, s = m0 & 1023;
        float* base = out + (h * 8 + b_) * DK * SEQ + s;
#pragma unroll
        for (int j = 0; j < 4; j++) {
            const int c = (n0 & 63) + j;
            float4 o = make_float4(accf[0][j] + bb[j], accf[1][j] + bb[j],
                                   accf[2][j] + bb[j], accf[3][j] + bb[j]);
            *(float4*)(base + c * SEQ) = o;
        }
    }
}

// =================================================================
// Fused attention, 512 threads (R9 layout) with FFMA2 inner loops.
// One CTA = 32 queries of one n = h*8+b.
// =================================================================
#define KVBUF 8704                                           /* floats */
#define SQ_FLOATS 2048
#define SS_FLOATS (32 * SSTRIDE)                             /* 32800 */
#define ATTN_SMEM_BYTES ((SQ_FLOATS + SS_FLOATS + 2*KVBUF) * 4) /* 209024 */

__device__ __forceinline__ void load_k_chunk(float* buf, const float* gK, int kc, int tid) {
#pragma unroll
    for (int j = 0; j < 4; j++) {                     // 2048 float4 / 512 thr
        int f = tid + 512 * j;
        int c = f >> 5;
        int kk = (f & 31) << 2;
        cp16(buf + c * 128 + kk, gK + c * SEQ + kc * 128 + kk);
    }
}
__device__ __forceinline__ void load_v_chunk(float* buf, const float* gV, int kc, int tid) {
#pragma unroll
    for (int j = 0; j < 4; j++) {
        int f = tid + 512 * j;
        int key = f >> 4;
        int c4 = (f & 15) << 2;
        cp16(buf + key * 68 + c4, gV + (kc * 128 + key) * DK + c4);
    }
}

__global__ void __launch_bounds__(512, 1) attn_kernel(const int* __restrict__ randidx, int n_rand)
{
    extern __shared__ float sm[];
    float* sQt  = sm;                        // [64][32]
    float* sS   = sm + SQ_FLOATS;            // [32][1025]
    float* sKV0 = sm + SQ_FLOATS + SS_FLOATS;
    float* sKV1 = sKV0 + KVBUF;
    __shared__ unsigned sRand[32];

    const int tid  = threadIdx.x;
    const int lane = tid & 31;
    const int warp = tid >> 5;               // 0..15
    const int qb = blockIdx.x;               // 0..31
    const int n  = blockIdx.y;               // h*8 + b

    const float* gQ = g_Qt + n * (DK * SEQ);
    const float* gK = g_Kt + n * (DK * SEQ);
    const float* gV = g_V  + n * (SEQ * DK);

    load_k_chunk(sKV0, gK, 0, tid);          // kick off K chunk 0
    cp_commit();

    if (tid < 32) sRand[tid] = 0u;
    {   // Q tile (pre-scaled by 1/sqrt(64)): 512 float4, one per thread
        int c = tid >> 3, s4 = (tid & 7) << 2;
        float4 v = *(const float4*)(gQ + c * SEQ + qb * 32 + s4);
        v.x *= 0.125f; v.y *= 0.125f; v.z *= 0.125f; v.w *= 0.125f;
        *(float4*)(sQt + c * 32 + s4) = v;
    }
    __syncthreads();
    if (tid < n_rand) {
        int v = randidx[tid] & (SEQ - 1);
        atomicOr(&sRand[v >> 5], 1u << (v & 31));
    }

    // ---- scores: thread = 4 rows x 2 keys (packed over keys) ----
    {
        const int rowg = tid & 7;            // Q float4: 8 distinct/warp (1 phase)
        const int keyg = tid >> 3;           // K b64: 4 distinct/warp (1 phase)
        const int r0 = rowg * 4;
        const int key0 = keyg * 2;
        const float* qp = sQt + r0;
        for (int kc = 0; kc < 8; kc++) {
            if (kc < 7) {
                load_k_chunk((kc & 1) ? sKV0 : sKV1, gK, kc + 1, tid);
                cp_commit();
                cp_wait1();
            } else {
                cp_wait0();
            }
            __syncthreads();
            const float* kp = ((kc & 1) ? sKV1 : sKV0) + key0;
            uint64_t acc0 = 0, acc1 = 0, acc2 = 0, acc3 = 0;  // rows 0..3 x (k0,k1)
#pragma unroll 16
            for (int c = 0; c < 64; c++) {
                const float4 q = *(const float4*)(qp + c * 32);          // 8-way dedup
                const uint64_t k2 = *(const uint64_t*)(kp + c * 128);    // packed (k0,k1)
                fma2(acc0, dup2(q.x), k2);
                fma2(acc1, dup2(q.y), k2);
                fma2(acc2, dup2(q.z), k2);
                fma2(acc3, dup2(q.w), k2);
            }
            float* sp = sS + r0 * SSTRIDE + kc * 128 + key0;
            const float2 r0v = unpack2(acc0), r1v = unpack2(acc1);
            const float2 r2v = unpack2(acc2), r3v = unpack2(acc3);
            sp[0] = r0v.x;              sp[1] = r0v.y;
            sp[SSTRIDE] = r1v.x;        sp[SSTRIDE + 1] = r1v.y;
            sp[2 * SSTRIDE] = r2v.x;    sp[2 * SSTRIDE + 1] = r2v.y;
            sp[3 * SSTRIDE] = r3v.x;    sp[3 * SSTRIDE + 1] = r3v.y;
            __syncthreads();
        }
    }

    load_v_chunk(sKV0, gV, 0, tid);          // prefetch V chunk 0 (overlaps topk)
    cp_commit();

    // ---- exp + exact top-51 (early-exit radix) + rand-mask + renorm ----
    {
#pragma unroll 1
        for (int rr = 0; rr < 2; rr++) {
            const int r = warp * 2 + rr;
            float* row = sS + r * SSTRIDE;
            float e[32];
            float m = -3.0e38f;
#pragma unroll
            for (int i = 0; i < 32; i++) { e[i] = row[lane + 32 * i]; m = fmaxf(m, e[i]); }
#pragma unroll
            for (int off = 16; off; off >>= 1) m = fmaxf(m, __shfl_xor_sync(0xFFFFFFFFu, m, off));
#pragma unroll
            for (int i = 0; i < 32; i++) e[i] = ex2f((e[i] - m) * 1.4426950408889634f);

            unsigned prefix = 0u;
#pragma unroll 1
            for (int bit = 29; bit >= 0; bit--) {
                const unsigned cand = prefix | (1u << bit);
                int c = 0;
#pragma unroll
                for (int i = 0; i < 32; i++) c += (__float_as_uint(e[i]) >= cand) ? 1 : 0;
                c = __reduce_add_sync(0xFFFFFFFFu, c);
                if (c >= TOPK) {
                    prefix = cand;
                    if (c == TOPK) break;   // exact set resolved
                }
            }

            float s = 0.0f;
#pragma unroll
            for (int i = 0; i < 32; i++) {
                bool sel = (__float_as_uint(e[i]) >= prefix) || ((sRand[i] >> lane) & 1u);
                e[i] = sel ? e[i] * SCALE : e[i];
                s += e[i];
            }
#pragma unroll
            for (int off = 16; off; off >>= 1) s += __shfl_xor_sync(0xFFFFFFFFu, s, off);
            const float inv = 1.0f / s;
#pragma unroll
            for (int i = 0; i < 32; i++) row[lane + 32 * i] = e[i] * inv;
        }
    }

    // ---- AV: thread = 4 rows x 4 cols (packed over col pairs), 4-way k-split ----
    {
        const int t128 = tid & 127;
        const int rowg = t128 & 7;           // S scalars: 8 distinct rows/warp
        const int colg = (t128 >> 3) & 15;   // V: 4 distinct/warp
        const int kq   = tid >> 7;           // 0..3: k-quarter of each chunk
        const int r0 = rowg * 4;
        const int c0 = colg * 4;
        const int kb = kq * 32;
        uint64_t accA[4] = {}, accB[4] = {}; // [row] x (c0,c1) and (c2,c3)
        for (int kc = 0; kc < 8; kc++) {
            if (kc < 7) {
                load_v_chunk((kc & 1) ? sKV0 : sKV1, gV, kc + 1, tid);
                cp_commit();
                cp_wait1();
            } else {
                cp_wait0();
            }
            __syncthreads();
            const float* Vb = ((kc & 1) ? sKV1 : sKV0) + c0;
            const float* Sb = sS + r0 * SSTRIDE + kc * 128;
#pragma unroll 4
            for (int k = kb; k < kb + 32; k++) {
                const ulonglong2 v2 = *(const ulonglong2*)(Vb + k * 68); // (v0,v1),(v2,v3)
                const uint64_t d0 = dup2(Sb[k]);
                const uint64_t d1 = dup2(Sb[SSTRIDE + k]);
                const uint64_t d2 = dup2(Sb[2 * SSTRIDE + k]);
                const uint64_t d3 = dup2(Sb[3 * SSTRIDE + k]);
                fma2(accA[0], d0, v2.x); fma2(accB[0], d0, v2.y);
                fma2(accA[1], d1, v2.x); fma2(accB[1], d1, v2.y);
                fma2(accA[2], d2, v2.x); fma2(accB[2], d2, v2.y);
                fma2(accA[3], d3, v2.x); fma2(accB[3], d3, v2.y);
            }
            __syncthreads();
        }

        float acc[4][4];
#pragma unroll
        for (int i = 0; i < 4; i++) {
            const float2 pa = unpack2(accA[i]);
            const float2 pb = unpack2(accB[i]);
            acc[i][0] = pa.x; acc[i][1] = pa.y; acc[i][2] = pb.x; acc[i][3] = pb.y;
        }

        // reduce the 4 kq-partials through sKV0 (free after last V chunk)
        float* scratch = sKV0;
        if (kq != 0) {
            float* dst = scratch + ((kq - 1) * 128 + t128) * 16;
#pragma unroll
            for (int i = 0; i < 4; i++)
                *(float4*)(dst + i * 4) = make_float4(acc[i][0], acc[i][1], acc[i][2], acc[i][3]);
        }
        __syncthreads();
        if (kq == 0) {
#pragma unroll
            for (int p = 0; p < 3; p++) {
                const float* src = scratch + (p * 128 + t128) * 16;
#pragma unroll
                for (int i = 0; i < 4; i++) {
                    const float4 t = *(const float4*)(src + i * 4);
                    acc[i][0] += t.x; acc[i][1] += t.y; acc[i][2] += t.z; acc[i][3] += t.w;
                }
            }
            // write to g_attn[b][s][h*64+c]
            const int h = n >> 3, b_ = n & 7;
            const int s = qb * 32 + r0;
            float* ob = g_attn + (b_ * SEQ + s) * HID + h * 64 + c0;
#pragma unroll
            for (int i = 0; i < 4; i++)
                *(float4*)(ob + i * HID) = make_float4(acc[i][0], acc[i][1], acc[i][2], acc[i][3]);
        }
    }
}

// =================================================================
extern "C" void kernel_launch(void* const* d_in, const int* in_sizes, int n_in,
                              void* d_out, int out_size) {
    const float* Qx  = (const float*)d_in[0];
    const float* KVx = (const float*)d_in[1];
    const float* Wq  = (const float*)d_in[2];
    const float* bq  = (const float*)d_in[3];
    const float* Wk  = (const float*)d_in[4];
    const float* bk  = (const float*)d_in[5];
    const float* Wv  = (const float*)d_in[6];
    const float* bv  = (const float*)d_in[7];
    const float* Wo  = (const float*)d_in[8];
    const float* bo  = (const float*)d_in[9];
    const int* ridx  = (const int*)d_in[10];
    const int n_rand = in_sizes[10];
    float* out = (float*)d_out;

    float *pQt, *pKt, *pV, *pA;
    cudaGetSymbolAddress((void**)&pQt, g_Qt);
    cudaGetSymbolAddress((void**)&pKt, g_Kt);
    cudaGetSymbolAddress((void**)&pV,  g_V);
    cudaGetSymbolAddress((void**)&pA,  g_attn);

    cudaFuncSetAttribute(attn_kernel, cudaFuncAttributeMaxDynamicSharedMemorySize, ATTN_SMEM_BYTES);

    dim3 gg(8, 128);   // N tiles (512/64), M tiles (8192/64)
    sgemm512<<<gg, 256>>>(Qx,  Wq, bq, pQt, 0);
    sgemm512<<<gg, 256>>>(KVx, Wk, bk, pKt, 0);
    sgemm512<<<gg, 256>>>(KVx, Wv, bv, pV,  1);
    attn_kernel<<<dim3(32, 64), 512, ATTN_SMEM_BYTES>>>(ridx, n_rand);
    sgemm512<<<gg, 256>>>(pA, Wo, bo, out, 2);
}